// round 2
// baseline (speedup 1.0000x reference)
#include <cuda_runtime.h>
#include <math.h>

// Problem constants
#define BATCH 4
#define SEQ   2048
#define DIM   768

// Scratch (allocation-free: __device__ globals)
__device__ float g_q[(size_t)BATCH * SEQ * DIM];
__device__ float g_k[(size_t)BATCH * SEQ * DIM];
__device__ float g_v[(size_t)BATCH * SEQ * DIM];
__device__ float g_s[(size_t)BATCH * SEQ * SEQ];

// ----------------------------------------------------------------------------
// Tiled fp32 GEMM: C = alpha * A @ op(B) (+ bias)
//   A: [M,K] row-major
//   TRANSB=false: B is [K,N] row-major (NN)
//   TRANSB=true : B is [N,K] row-major, use B^T (NT)
//   Tile: BM=BN=128, BK=16; 256 threads; 8x8 per-thread microtile.
//   Requires M%128==0, N%128==0, K%16==0 (true for all shapes here).
//   blockIdx.z batches via strides sA/sB/sC.
// ----------------------------------------------------------------------------
template <bool TRANSB, bool BIAS>
__global__ __launch_bounds__(256, 2)
void gemm128(const float* __restrict__ A, const float* __restrict__ B,
             const float* __restrict__ bias, float* __restrict__ C,
             int M, int N, int K, float alpha,
             size_t sA, size_t sB, size_t sC)
{
    constexpr int BM = 128, BN = 128, BK = 16;

    A += (size_t)blockIdx.z * sA;
    B += (size_t)blockIdx.z * sB;
    C += (size_t)blockIdx.z * sC;

    __shared__ float As[BK][BM];
    __shared__ float Bs[BK][BN];

    const int tid = threadIdx.x;
    const int tx  = tid & 15;   // n-direction (0..15) -> 8 cols each
    const int ty  = tid >> 4;   // m-direction (0..15) -> 8 rows each
    const int m0  = blockIdx.y * BM;
    const int n0  = blockIdx.x * BN;

    // K-strided (scatter) load pattern: element group e -> row=e/4, kvec=(e%4)*4
    const int ld_row = tid >> 2;         // 0..63 (+64 on second pass)
    const int ld_kv  = (tid & 3) * 4;    // 0,4,8,12

    float acc[8][8];
#pragma unroll
    for (int i = 0; i < 8; i++)
#pragma unroll
        for (int j = 0; j < 8; j++) acc[i][j] = 0.0f;

    for (int kt = 0; kt < K; kt += BK) {
        // --- load A tile [BM x BK] -> As[k][m] ---
#pragma unroll
        for (int r = 0; r < 2; r++) {
            const int row = ld_row + r * 64;
            const float4 va = *reinterpret_cast<const float4*>(
                &A[(size_t)(m0 + row) * K + kt + ld_kv]);
            As[ld_kv + 0][row] = va.x;
            As[ld_kv + 1][row] = va.y;
            As[ld_kv + 2][row] = va.z;
            As[ld_kv + 3][row] = va.w;
        }
        // --- load B tile -> Bs[k][n] ---
        if (TRANSB) {
            // B is [N,K]; Bs[k][n] = B[n0+n][kt+k]
#pragma unroll
            for (int r = 0; r < 2; r++) {
                const int n = ld_row + r * 64;
                const float4 vb = *reinterpret_cast<const float4*>(
                    &B[(size_t)(n0 + n) * K + kt + ld_kv]);
                Bs[ld_kv + 0][n] = vb.x;
                Bs[ld_kv + 1][n] = vb.y;
                Bs[ld_kv + 2][n] = vb.z;
                Bs[ld_kv + 3][n] = vb.w;
            }
        } else {
            // B is [K,N]; contiguous along n
#pragma unroll
            for (int r = 0; r < 2; r++) {
                const int e  = tid + r * 256;
                const int k  = e >> 5;          // 0..15
                const int nv = (e & 31) * 4;    // 0..124
                *reinterpret_cast<float4*>(&Bs[k][nv]) =
                    *reinterpret_cast<const float4*>(
                        &B[(size_t)(kt + k) * N + n0 + nv]);
            }
        }
        __syncthreads();

#pragma unroll
        for (int k = 0; k < BK; k++) {
            float a[8], b[8];
            *reinterpret_cast<float4*>(&a[0]) =
                *reinterpret_cast<const float4*>(&As[k][ty * 8]);
            *reinterpret_cast<float4*>(&a[4]) =
                *reinterpret_cast<const float4*>(&As[k][ty * 8 + 4]);
            *reinterpret_cast<float4*>(&b[0]) =
                *reinterpret_cast<const float4*>(&Bs[k][tx * 8]);
            *reinterpret_cast<float4*>(&b[4]) =
                *reinterpret_cast<const float4*>(&Bs[k][tx * 8 + 4]);
#pragma unroll
            for (int i = 0; i < 8; i++)
#pragma unroll
                for (int j = 0; j < 8; j++)
                    acc[i][j] = fmaf(a[i], b[j], acc[i][j]);
        }
        __syncthreads();
    }

    // --- epilogue ---
#pragma unroll
    for (int i = 0; i < 8; i++) {
        const size_t crow = (size_t)(m0 + ty * 8 + i) * N + n0 + tx * 8;
#pragma unroll
        for (int jv = 0; jv < 2; jv++) {
            const int j = jv * 4;
            float4 v;
            v.x = acc[i][j + 0] * alpha;
            v.y = acc[i][j + 1] * alpha;
            v.z = acc[i][j + 2] * alpha;
            v.w = acc[i][j + 3] * alpha;
            if (BIAS) {
                const int nb = n0 + tx * 8 + j;
                v.x += bias[nb + 0];
                v.y += bias[nb + 1];
                v.z += bias[nb + 2];
                v.w += bias[nb + 3];
            }
            *reinterpret_cast<float4*>(&C[crow + j]) = v;
        }
    }
}

// ----------------------------------------------------------------------------
// Row softmax over SEQ=2048 columns. One block (256 threads) per row.
// ----------------------------------------------------------------------------
__global__ __launch_bounds__(256)
void softmax2048(float* __restrict__ S)
{
    float* p = S + (size_t)blockIdx.x * SEQ;
    const int tid = threadIdx.x;

    __shared__ float red_max[8];
    __shared__ float red_sum[8];

    float4* p4 = reinterpret_cast<float4*>(p);
    float4 vals[2];

    float m = -1e30f;
#pragma unroll
    for (int r = 0; r < 2; r++) {
        const float4 v = p4[tid + r * 256];
        vals[r] = v;
        m = fmaxf(m, fmaxf(fmaxf(v.x, v.y), fmaxf(v.z, v.w)));
    }
#pragma unroll
    for (int o = 16; o > 0; o >>= 1)
        m = fmaxf(m, __shfl_xor_sync(0xffffffffu, m, o));
    if ((tid & 31) == 0) red_max[tid >> 5] = m;
    __syncthreads();
    float rm = red_max[0];
#pragma unroll
    for (int i = 1; i < 8; i++) rm = fmaxf(rm, red_max[i]);

    float s = 0.0f;
#pragma unroll
    for (int r = 0; r < 2; r++) {
        float4 v = vals[r];
        v.x = __expf(v.x - rm);
        v.y = __expf(v.y - rm);
        v.z = __expf(v.z - rm);
        v.w = __expf(v.w - rm);
        s += v.x + v.y + v.z + v.w;
        vals[r] = v;
    }
#pragma unroll
    for (int o = 16; o > 0; o >>= 1)
        s += __shfl_xor_sync(0xffffffffu, s, o);
    if ((tid & 31) == 0) red_sum[tid >> 5] = s;
    __syncthreads();
    float total = 0.0f;
#pragma unroll
    for (int i = 0; i < 8; i++) total += red_sum[i];
    const float inv = 1.0f / total;

#pragma unroll
    for (int r = 0; r < 2; r++) {
        float4 v = vals[r];
        v.x *= inv; v.y *= inv; v.z *= inv; v.w *= inv;
        p4[tid + r * 256] = v;
    }
}

// ----------------------------------------------------------------------------
// kernel_launch
// Inputs (metadata order): x[B,S,D], Wq[D,D], bq[D], Wk, bk, Wv, bv
// Output: [B,S,D] float32
// ----------------------------------------------------------------------------
extern "C" void kernel_launch(void* const* d_in, const int* in_sizes, int n_in,
                              void* d_out, int out_size)
{
    const float* x  = (const float*)d_in[0];
    const float* Wq = (const float*)d_in[1];
    const float* bq = (const float*)d_in[2];
    const float* Wk = (const float*)d_in[3];
    const float* bk = (const float*)d_in[4];
    const float* Wv = (const float*)d_in[5];
    const float* bv = (const float*)d_in[6];
    float* out = (float*)d_out;

    float *q, *k, *v, *s;
    cudaGetSymbolAddress((void**)&q, g_q);
    cudaGetSymbolAddress((void**)&k, g_k);
    cudaGetSymbolAddress((void**)&v, g_v);
    cudaGetSymbolAddress((void**)&s, g_s);

    const dim3 blk(256);
    const size_t sdSD = (size_t)SEQ * DIM;   // per-batch stride for q/k/v/out
    const size_t sdSS = (size_t)SEQ * SEQ;   // per-batch stride for scores

    // 1) QKV projections: [B*S, D] @ [D, D] + bias
    {
        const dim3 grid(DIM / 128, (BATCH * SEQ) / 128, 1);
        gemm128<false, true><<<grid, blk>>>(x, Wq, bq, q,
                                            BATCH * SEQ, DIM, DIM, 1.0f, 0, 0, 0);
        gemm128<false, true><<<grid, blk>>>(x, Wk, bk, k,
                                            BATCH * SEQ, DIM, DIM, 1.0f, 0, 0, 0);
        gemm128<false, true><<<grid, blk>>>(x, Wv, bv, v,
                                            BATCH * SEQ, DIM, DIM, 1.0f, 0, 0, 0);
    }

    // 2) scores = Q @ K^T / sqrt(D)  (batched, NT)
    {
        const dim3 grid(SEQ / 128, SEQ / 128, BATCH);
        const float alpha = rsqrtf((float)DIM);
        gemm128<true, false><<<grid, blk>>>(q, k, nullptr, s,
                                            SEQ, SEQ, DIM, alpha,
                                            sdSD, sdSD, sdSS);
    }

    // 3) row softmax over scores
    softmax2048<<<BATCH * SEQ, 256>>>(s);

    // 4) out = attn @ V  (batched, NN)
    {
        const dim3 grid(DIM / 128, SEQ / 128, BATCH);
        gemm128<false, false><<<grid, blk>>>(s, v, nullptr, out,
                                             SEQ, DIM, SEQ, 1.0f,
                                             sdSS, sdSD, sdSD);
    }
}

// round 4
// speedup vs baseline: 3.6456x; 3.6456x over previous
#include <cuda_runtime.h>
#include <math.h>
#include <stdint.h>

// Problem constants
#define BATCH 4
#define SEQ   2048
#define DIM   768

// Scratch (allocation-free: __device__ globals)
__device__ float g_q [(size_t)BATCH * SEQ * DIM];
__device__ float g_k [(size_t)BATCH * SEQ * DIM];
__device__ float g_v [(size_t)BATCH * SEQ * DIM];
__device__ float g_vt[(size_t)BATCH * SEQ * DIM];
__device__ float g_s [(size_t)BATCH * SEQ * SEQ];
__device__ float g_wt[3][DIM * DIM];

// ----------------------------------------------------------------------------
// helpers
// ----------------------------------------------------------------------------
__device__ __forceinline__ uint32_t smem_u32(const void* p) {
    uint32_t a;
    asm("{ .reg .u64 t; cvta.to.shared.u64 t, %1; cvt.u32.u64 %0, t; }"
        : "=r"(a) : "l"(p));
    return a;
}
__device__ __forceinline__ uint32_t f2tf32(float f) {
    uint32_t r;
    asm("cvt.rna.tf32.f32 %0, %1;" : "=r"(r) : "f"(f));
    return r;
}
__device__ __forceinline__ void cp_async16(uint32_t dst, const void* src) {
    asm volatile("cp.async.cg.shared.global [%0], [%1], 16;"
                 :: "r"(dst), "l"(src));
}
__device__ __forceinline__ void cp_commit() {
    asm volatile("cp.async.commit_group;" ::: "memory");
}
__device__ __forceinline__ void cp_wait1() {
    asm volatile("cp.async.wait_group 1;" ::: "memory");
}
__device__ __forceinline__ void cp_wait0() {
    asm volatile("cp.async.wait_group 0;" ::: "memory");
}
__device__ __forceinline__ void mma_tf32(float* c, const uint32_t* a,
                                         const uint32_t* b) {
    asm volatile(
        "mma.sync.aligned.m16n8k8.row.col.f32.tf32.tf32.f32 "
        "{%0,%1,%2,%3}, {%4,%5,%6,%7}, {%8,%9}, {%0,%1,%2,%3};"
        : "+f"(c[0]), "+f"(c[1]), "+f"(c[2]), "+f"(c[3])
        : "r"(a[0]), "r"(a[1]), "r"(a[2]), "r"(a[3]),
          "r"(b[0]), "r"(b[1]));
}

// ----------------------------------------------------------------------------
// tf32 tensor-core GEMM (NT): C = alpha * A @ B^T (+ bias)
//   A: [M,K] row-major (lda), B: [N,K] row-major (ldb), C: [M,N] (ldc)
//   CTA tile 128x128, BK=32, cp.async 2-stage pipeline, 256 threads (8 warps).
//   Warp tile 64x32: 4x4 m16n8k8 atoms. SMEM stride 36 -> conflict-free frags.
//   Requires M%128==0, N%128==0, K%32==0.
// ----------------------------------------------------------------------------
#define SM_STRIDE 36          // 32 floats + 4 pad
#define STAGE_F   (2 * 128 * SM_STRIDE)   // floats per stage (A tile + B tile)

template <bool BIAS>
__global__ __launch_bounds__(256, 2)
void gemm_mma(const float* __restrict__ A, const float* __restrict__ B,
              const float* __restrict__ bias, float* __restrict__ C,
              int K, int lda, int ldb, int ldc, float alpha,
              size_t sA, size_t sB, size_t sC)
{
    extern __shared__ float sm[];

    const int tid  = threadIdx.x;
    const int wid  = tid >> 5;
    const int lane = tid & 31;
    const int grp  = lane >> 2;     // 0..7
    const int tg   = lane & 3;      // 0..3
    const int wm0  = (wid & 1) * 64;    // warp m offset in CTA tile
    const int wn0  = (wid >> 1) * 32;   // warp n offset

    A += (size_t)blockIdx.z * sA;
    B += (size_t)blockIdx.z * sB;
    C += (size_t)blockIdx.z * sC;
    const int m0 = blockIdx.y * 128;
    const int n0 = blockIdx.x * 128;

    // load indices for gmem->smem (16B granules): 1024 granules per matrix
    const int ld_row = tid >> 3;        // 0..31 (+32 per r-pass) -> tile row
    const int ld_seg = tid & 7;         // 16B segment within 128B row

    float acc[4][4][4];
#pragma unroll
    for (int im = 0; im < 4; im++)
#pragma unroll
        for (int in = 0; in < 4; in++)
#pragma unroll
            for (int r = 0; r < 4; r++) acc[im][in][r] = 0.0f;

    const int nch = K >> 5;

    // ---- tile loader (stage = c&1) ----
    auto load_tile = [&](int c) {
        const int kt = c << 5;
        float* as = sm + (c & 1) * STAGE_F;
        float* bs = as + 128 * SM_STRIDE;
        const uint32_t as_u = smem_u32(as);
        const uint32_t bs_u = smem_u32(bs);
#pragma unroll
        for (int r = 0; r < 4; r++) {
            const int row = ld_row + r * 32;
            cp_async16(as_u + (uint32_t)(row * SM_STRIDE + ld_seg * 4) * 4,
                       A + (size_t)(m0 + row) * lda + kt + ld_seg * 4);
        }
#pragma unroll
        for (int r = 0; r < 4; r++) {
            const int row = ld_row + r * 32;
            cp_async16(bs_u + (uint32_t)(row * SM_STRIDE + ld_seg * 4) * 4,
                       B + (size_t)(n0 + row) * ldb + kt + ld_seg * 4);
        }
    };

    load_tile(0);
    cp_commit();

    for (int c = 0; c < nch; c++) {
        if (c + 1 < nch) {
            load_tile(c + 1);
            cp_commit();
            cp_wait1();
        } else {
            cp_wait0();
        }
        __syncthreads();

        const float* as = sm + (c & 1) * STAGE_F;
        const float* bs = as + 128 * SM_STRIDE;

#pragma unroll
        for (int ks = 0; ks < 4; ks++) {
            const int kc = ks * 8 + tg;
            uint32_t af[4][4];
#pragma unroll
            for (int im = 0; im < 4; im++) {
                const float* ap = as + (wm0 + im * 16 + grp) * SM_STRIDE + kc;
                af[im][0] = f2tf32(ap[0]);
                af[im][1] = f2tf32(ap[8 * SM_STRIDE]);
                af[im][2] = f2tf32(ap[4]);
                af[im][3] = f2tf32(ap[8 * SM_STRIDE + 4]);
            }
            uint32_t bf[4][2];
#pragma unroll
            for (int in = 0; in < 4; in++) {
                const float* bp = bs + (wn0 + in * 8 + grp) * SM_STRIDE + kc;
                bf[in][0] = f2tf32(bp[0]);
                bf[in][1] = f2tf32(bp[4]);
            }
#pragma unroll
            for (int im = 0; im < 4; im++)
#pragma unroll
                for (int in = 0; in < 4; in++)
                    mma_tf32(acc[im][in], af[im], bf[in]);
        }
        __syncthreads();
    }

    // ---- epilogue: direct STG.64 per C fragment ----
#pragma unroll
    for (int im = 0; im < 4; im++) {
        const int row = m0 + wm0 + im * 16 + grp;
#pragma unroll
        for (int in = 0; in < 4; in++) {
            const int col = n0 + wn0 + in * 8 + tg * 2;
            float2 v01, v23;
            v01.x = acc[im][in][0] * alpha;
            v01.y = acc[im][in][1] * alpha;
            v23.x = acc[im][in][2] * alpha;
            v23.y = acc[im][in][3] * alpha;
            if (BIAS) {
                const float2 bv = *reinterpret_cast<const float2*>(bias + col);
                v01.x += bv.x; v01.y += bv.y;
                v23.x += bv.x; v23.y += bv.y;
            }
            *reinterpret_cast<float2*>(C + (size_t)row * ldc + col) = v01;
            *reinterpret_cast<float2*>(C + (size_t)(row + 8) * ldc + col) = v23;
        }
    }
}

// ----------------------------------------------------------------------------
// 32x32 tiled transpose: dst[c*R + r] = src[r*C + c]   (batched via z)
// ----------------------------------------------------------------------------
__global__ __launch_bounds__(256)
void transpose_k(const float* __restrict__ src, float* __restrict__ dst,
                 int R, int C, size_t sS, size_t sD)
{
    __shared__ float t[32][33];
    src += (size_t)blockIdx.z * sS;
    dst += (size_t)blockIdx.z * sD;
    const int r0 = blockIdx.y * 32, c0 = blockIdx.x * 32;
    const int tx = threadIdx.x & 31, ty = threadIdx.x >> 5;   // 32 x 8
#pragma unroll
    for (int i = 0; i < 4; i++)
        t[ty + 8 * i][tx] = src[(size_t)(r0 + ty + 8 * i) * C + c0 + tx];
    __syncthreads();
#pragma unroll
    for (int i = 0; i < 4; i++)
        dst[(size_t)(c0 + ty + 8 * i) * R + r0 + tx] = t[tx][ty + 8 * i];
}

// ----------------------------------------------------------------------------
// Row softmax over SEQ=2048 columns. One block (256 threads) per row.
// ----------------------------------------------------------------------------
__global__ __launch_bounds__(256)
void softmax2048(float* __restrict__ S)
{
    float* p = S + (size_t)blockIdx.x * SEQ;
    const int tid = threadIdx.x;
    __shared__ float red_max[8];
    __shared__ float red_sum[8];

    float4* p4 = reinterpret_cast<float4*>(p);
    float4 vals[2];

    float m = -1e30f;
#pragma unroll
    for (int r = 0; r < 2; r++) {
        const float4 v = p4[tid + r * 256];
        vals[r] = v;
        m = fmaxf(m, fmaxf(fmaxf(v.x, v.y), fmaxf(v.z, v.w)));
    }
#pragma unroll
    for (int o = 16; o > 0; o >>= 1)
        m = fmaxf(m, __shfl_xor_sync(0xffffffffu, m, o));
    if ((tid & 31) == 0) red_max[tid >> 5] = m;
    __syncthreads();
    float rm = red_max[0];
#pragma unroll
    for (int i = 1; i < 8; i++) rm = fmaxf(rm, red_max[i]);

    float s = 0.0f;
#pragma unroll
    for (int r = 0; r < 2; r++) {
        float4 v = vals[r];
        v.x = __expf(v.x - rm);
        v.y = __expf(v.y - rm);
        v.z = __expf(v.z - rm);
        v.w = __expf(v.w - rm);
        s += v.x + v.y + v.z + v.w;
        vals[r] = v;
    }
#pragma unroll
    for (int o = 16; o > 0; o >>= 1)
        s += __shfl_xor_sync(0xffffffffu, s, o);
    if ((tid & 31) == 0) red_sum[tid >> 5] = s;
    __syncthreads();
    float total = 0.0f;
#pragma unroll
    for (int i = 0; i < 8; i++) total += red_sum[i];
    const float inv = 1.0f / total;

#pragma unroll
    for (int r = 0; r < 2; r++) {
        float4 v = vals[r];
        v.x *= inv; v.y *= inv; v.z *= inv; v.w *= inv;
        p4[tid + r * 256] = v;
    }
}

// ----------------------------------------------------------------------------
// kernel_launch
// Inputs: x[B,S,D], Wq[D,D], bq[D], Wk, bk, Wv, bv ; output [B,S,D] fp32
// ----------------------------------------------------------------------------
extern "C" void kernel_launch(void* const* d_in, const int* in_sizes, int n_in,
                              void* d_out, int out_size)
{
    const float* x  = (const float*)d_in[0];
    const float* Wq = (const float*)d_in[1];
    const float* bq = (const float*)d_in[2];
    const float* Wk = (const float*)d_in[3];
    const float* bk = (const float*)d_in[4];
    const float* Wv = (const float*)d_in[5];
    const float* bv = (const float*)d_in[6];
    float* out = (float*)d_out;

    float *q, *k, *v, *vt, *s, *wt;
    cudaGetSymbolAddress((void**)&q,  g_q);
    cudaGetSymbolAddress((void**)&k,  g_k);
    cudaGetSymbolAddress((void**)&v,  g_v);
    cudaGetSymbolAddress((void**)&vt, g_vt);
    cudaGetSymbolAddress((void**)&s,  g_s);
    cudaGetSymbolAddress((void**)&wt, g_wt);
    float* wqt = wt;
    float* wkt = wt + (size_t)DIM * DIM;
    float* wvt = wt + 2 * (size_t)DIM * DIM;

    const int SMEM_DYN = 2 * STAGE_F * (int)sizeof(float);   // 73728 B
    cudaFuncSetAttribute(gemm_mma<true>,
                         cudaFuncAttributeMaxDynamicSharedMemorySize, SMEM_DYN);
    cudaFuncSetAttribute(gemm_mma<false>,
                         cudaFuncAttributeMaxDynamicSharedMemorySize, SMEM_DYN);

    const size_t sdSD = (size_t)SEQ * DIM;
    const size_t sdSS = (size_t)SEQ * SEQ;
    const dim3 blk(256);

    // 0) transpose weights: W[D,D] -> W^T (so QKV GEMMs are NT)
    {
        const dim3 g(DIM / 32, DIM / 32, 1);
        transpose_k<<<g, blk>>>(Wq, wqt, DIM, DIM, 0, 0);
        transpose_k<<<g, blk>>>(Wk, wkt, DIM, DIM, 0, 0);
        transpose_k<<<g, blk>>>(Wv, wvt, DIM, DIM, 0, 0);
    }

    // 1) QKV projections: [8192,768] = x @ W^T (NT) + bias
    {
        const dim3 g(DIM / 128, (BATCH * SEQ) / 128, 1);
        gemm_mma<true><<<g, blk, SMEM_DYN>>>(x, wqt, bq, q,
                                             DIM, DIM, DIM, DIM, 1.0f, 0, 0, 0);
        gemm_mma<true><<<g, blk, SMEM_DYN>>>(x, wkt, bk, k,
                                             DIM, DIM, DIM, DIM, 1.0f, 0, 0, 0);
        gemm_mma<true><<<g, blk, SMEM_DYN>>>(x, wvt, bv, v,
                                             DIM, DIM, DIM, DIM, 1.0f, 0, 0, 0);
    }

    // 2) transpose V: [S,D] -> [D,S] per batch (so attn@V is NT)
    {
        const dim3 g(DIM / 32, SEQ / 32, BATCH);
        transpose_k<<<g, blk>>>(v, vt, SEQ, DIM, sdSD, sdSD);
    }

    // 3) scores = Q @ K^T / sqrt(D)  (NT)
    {
        const dim3 g(SEQ / 128, SEQ / 128, BATCH);
        gemm_mma<false><<<g, blk, SMEM_DYN>>>(q, k, nullptr, s,
                                              DIM, DIM, DIM, SEQ,
                                              rsqrtf((float)DIM),
                                              sdSD, sdSD, sdSS);
    }

    // 4) softmax rows
    softmax2048<<<BATCH * SEQ, 256>>>(s);

    // 5) out = attn @ V == s[S,S] @ (vt[D,S])^T  (NT)
    {
        const dim3 g(DIM / 128, SEQ / 128, BATCH);
        gemm_mma<false><<<g, blk, SMEM_DYN>>>(s, vt, nullptr, out,
                                              SEQ, SEQ, SEQ, DIM, 1.0f,
                                              sdSS, sdSD, sdSD);
    }
}